// round 16
// baseline (speedup 1.0000x reference)
#include <cuda_runtime.h>
#include <cuda_bf16.h>
#include <cstdint>

// ---------------------------------------------------------------------------
// Fused Gaussian rasterizer, R16 = R14 (256 CTAs x 256 thr, 16x16 tiles,
// 2 gaussians/thread register projection, slot-parallel rank, vsub2 mask)
// with the composite tail restructured as a product tree:
//   loop-carried dependency = ONE multiply (T *= P) per batch of 4.
// ---------------------------------------------------------------------------

#define NG    512
#define IMG   256
#define TW    16
#define TH    16
#define NT    256
#define NWARP (NT/32)

__device__ __forceinline__ float ex2(float x) {
    float y;
    asm("ex2.approx.ftz.f32 %0, %1;" : "=f"(y) : "f"(x));
    return y;
}

__global__ __launch_bounds__(NT)
void gs_fused(const float* __restrict__ pos,
              const float* __restrict__ cov3d,
              const float* __restrict__ opac,
              const float* __restrict__ cols,
              const float* __restrict__ Km,
              const float* __restrict__ Rm,
              const float* __restrict__ tv,
              float* __restrict__ out)
{
    __shared__ float4             rec[NG + 4][3];  // ~24.2 KB
    __shared__ unsigned long long skey[NG];        // 4 KB
    __shared__ short              srank[NG];       // 1 KB
    __shared__ int                warpTotals[NWARP];

    const int tid  = threadIdx.x;
    const int lane = tid & 31;
    const int wid  = tid >> 5;

    const int tileX = blockIdx.x * TW;
    const int tileY = blockIdx.y * TH;

    const float r00 = Rm[0], r01 = Rm[1], r02 = Rm[2];
    const float r10 = Rm[3], r11 = Rm[4], r12 = Rm[5];
    const float r20 = Rm[6], r21 = Rm[7], r22 = Rm[8];
    const float fx  = Km[0], fy = Km[4];

    // ---------------- phase 1: project 2 gaussians/thread ----------------
    bool  flg[2];
    unsigned long long key[2];
    float4 R0v[2], R1v[2], R2v[2];

    #pragma unroll
    for (int s = 0; s < 2; s++) {
        const int g = tid + s * NT;
        const float p0 = pos[3*g+0], p1 = pos[3*g+1], p2 = pos[3*g+2];

        const float cam0 = r00*p0 + r01*p1 + r02*p2 + tv[0];
        const float cam1 = r10*p0 + r11*p1 + r12*p2 + tv[1];
        const float cam2 = r20*p0 + r21*p1 + r22*p2 + tv[2];

        const float pr0 = Km[0]*cam0 + Km[1]*cam1 + Km[2]*cam2;
        const float pr1 = Km[3]*cam0 + Km[4]*cam1 + Km[5]*cam2;
        const float pr2 = Km[6]*cam0 + Km[7]*cam1 + Km[8]*cam2;
        const float rz = 1.0f / pr2;
        const float mx = pr0 * rz;
        const float my = pr1 * rz;

        const float z   = cam2;
        const float iz  = 1.0f / z;
        const float jx0 = fx * iz;
        const float jx2 = -fx * cam0 * iz * iz;
        const float jy1 = fy * iz;
        const float jy2 = -fy * cam1 * iz * iz;

        // P = J * R  (2x3)
        const float P00 = jx0*r00 + jx2*r20;
        const float P01 = jx0*r01 + jx2*r21;
        const float P02 = jx0*r02 + jx2*r22;
        const float P10 = jy1*r10 + jy2*r20;
        const float P11 = jy1*r11 + jy2*r21;
        const float P12 = jy1*r12 + jy2*r22;

        // symmetric C
        const float c00 = cov3d[9*g+0];
        const float c01 = cov3d[9*g+1];
        const float c02 = cov3d[9*g+2];
        const float c11 = cov3d[9*g+4];
        const float c12 = cov3d[9*g+5];
        const float c22 = cov3d[9*g+8];

        const float t00 = c00*P00 + c01*P01 + c02*P02;
        const float t01 = c01*P00 + c11*P01 + c12*P02;
        const float t02 = c02*P00 + c12*P01 + c22*P02;
        const float t10 = c00*P10 + c01*P11 + c02*P12;
        const float t11 = c01*P10 + c11*P11 + c12*P12;
        const float t12 = c02*P10 + c12*P11 + c22*P12;

        const float a = P00*t00 + P01*t01 + P02*t02 + 0.3f;
        const float b = P10*t00 + P11*t01 + P12*t02;
        const float c = P10*t10 + P11*t11 + P12*t12 + 0.3f;

        const float det  = fmaxf(a*c - b*b, 1e-8f);
        const float idet = 1.0f / det;
        // exp2 prescale: exp(-0.5*m) = exp2(-0.72134752*m)
        const float e00 = -0.72134752f * c * idet;
        const float e01 =  1.44269504f * b * idet;
        const float e11 = -0.72134752f * a * idet;

        const float hd = (a - c) * 0.5f;
        const float max_eig = (a + c)*0.5f + sqrtf(fmaxf(hd*hd + b*b, 1e-8f));
        const float radius = 3.0f * sqrtf(max_eig);

        const float x_min = fmaxf(0.0f,       truncf(mx - radius));
        const float x_max = fminf((float)IMG, truncf(mx + radius) + 1.0f);
        const float y_min = fmaxf(0.0f,       truncf(my - radius));
        const float y_max = fminf((float)IMG, truncf(my + radius) + 1.0f);

        const float bias = __log2f(opac[g]);

        // u16-packed cull/mask words; empty boxes canonicalized to never-hit
        unsigned lo, hm1;
        if (x_max <= x_min || y_max <= y_min) {
            lo  = 0x7FFF7FFFu;
            hm1 = 0u;
        } else {
            lo  = (unsigned)x_min | ((unsigned)y_min << 16);
            hm1 = (unsigned)(x_max - 1.0f) | ((unsigned)(y_max - 1.0f) << 16);
        }

        const int x0  = (int)(lo & 0xffffu), y0  = (int)(lo >> 16);
        const int x1m = (int)(hm1 & 0xffffu), y1m = (int)(hm1 >> 16);
        flg[s] = (x0 < tileX + TW) & (x1m >= tileX) &
                 (y0 < tileY + TH) & (y1m >= tileY);
        key[s] = ((unsigned long long)__float_as_uint(z) << 16)
               | (unsigned long long)g;

        R0v[s] = make_float4(mx, my, e00, e01);
        R1v[s] = make_float4(e11, bias,
                             __uint_as_float(lo), __uint_as_float(hm1));
        R2v[s] = make_float4(cols[3*g+0], cols[3*g+1], cols[3*g+2], 0.f);
    }

    // ---------------- phase 2: compaction slots ----------------
    const unsigned m0 = __ballot_sync(0xffffffffu, flg[0]);
    const unsigned m1 = __ballot_sync(0xffffffffu, flg[1]);
    if (lane == 0) warpTotals[wid] = __popc(m0) | (__popc(m1) << 16);
    __syncthreads();

    int prefix = 0, total = 0;
    #pragma unroll
    for (int w = 0; w < NWARP; w++) {
        const int t = warpTotals[w];
        if (w < wid) prefix += t;
        total += t;
    }
    const int count0 = total & 0xffff;
    const int count  = count0 + (total >> 16);
    const unsigned lm = (1u << lane) - 1u;
    const int pos0 = (prefix & 0xffff) + __popc(m0 & lm);
    const int pos1 = count0 + (prefix >> 16) + __popc(m1 & lm);

    if (flg[0]) skey[pos0] = key[0];
    if (flg[1]) skey[pos1] = key[1];
    __syncthreads();

    // ---------------- phase 3: slot-parallel rank ----------------
    if (tid < count) {
        const unsigned long long k = skey[tid];
        int r = 0;
        for (int j = 0; j < count; j++)
            r += (skey[j] < k);
        srank[tid] = (short)r;
    }
    __syncthreads();

    // ---------------- phase 3b: owners scatter into depth order ----------
    if (flg[0]) {
        const int r = srank[pos0];
        rec[r][0] = R0v[0]; rec[r][1] = R1v[0]; rec[r][2] = R2v[0];
    }
    if (flg[1]) {
        const int r = srank[pos1];
        rec[r][0] = R0v[1]; rec[r][1] = R1v[1]; rec[r][2] = R2v[1];
    }
    const int countPad = (count + 3) & ~3;
    for (int t2 = count + tid; t2 < countPad; t2 += NT) {
        rec[t2][0] = make_float4(0.f, 0.f, 0.f, 0.f);
        rec[t2][1] = make_float4(0.f, 0.f,
                                 __uint_as_float(0x7FFF7FFFu), 0.f);
        rec[t2][2] = make_float4(0.f, 0.f, 0.f, 0.f);
    }
    __syncthreads();

    // ---------------- phase 4: composite, product-tree tail ----------------
    const int pxi = tileX + (tid & (TW - 1));
    const int pyi = tileY + (tid >> 4);
    const float pxf = (float)pxi;
    const float pyf = (float)pyi;
    const unsigned pxy = (unsigned)pxi | ((unsigned)pyi << 16);

    float T = 1.0f, rr = 0.0f, gg = 0.0f, bb = 0.0f;
    for (int base = 0; base < countPad; base += 4) {
        float4 q0[4], q1[4], q2[4];
        #pragma unroll
        for (int i = 0; i < 4; i++) {
            q0[i] = rec[base+i][0];
            q1[i] = rec[base+i][1];
            q2[i] = rec[base+i][2];
        }
        float av[4];
        #pragma unroll
        for (int i = 0; i < 4; i++) {
            const unsigned lo  = __float_as_uint(q1[i].z);
            const unsigned hm1 = __float_as_uint(q1[i].w);
            const unsigned ua  = __vsub2(pxy, lo);
            const unsigned ub  = __vsub2(hm1, pxy);
            const bool inb = ((ua | ub) & 0x80008000u) == 0u;

            const float dx = pxf - q0[i].x;
            const float dy = pyf - q0[i].y;
            const float u  = fmaf(q1[i].x * dy, dy, q1[i].y);   // e11*dy^2 + bias
            const float pl = fmaf(q0[i].w, dy, q0[i].z * dx);   // e01*dy + e00*dx
            const float e  = fmaf(pl, dx, u);
            av[i] = inb ? ex2(e) : 0.0f;                        // alpha
        }

        // product tree: loop-carried dep collapses to T *= P
        const float b0 = 1.0f - av[0];
        const float b1 = 1.0f - av[1];
        const float b2 = 1.0f - av[2];
        const float b3 = 1.0f - av[3];
        const float p01  = b0 * b1;
        const float p23  = b2 * b3;
        const float w0 = av[0];
        const float w1 = av[1] * b0;
        const float w2 = av[2] * p01;
        const float w3 = av[3] * (b2 * p01);
        const float P  = p01 * p23;

        const float sr = fmaf(w0, q2[0].x, w1 * q2[1].x)
                       + fmaf(w2, q2[2].x, w3 * q2[3].x);
        const float sg = fmaf(w0, q2[0].y, w1 * q2[1].y)
                       + fmaf(w2, q2[2].y, w3 * q2[3].y);
        const float sb = fmaf(w0, q2[0].z, w1 * q2[1].z)
                       + fmaf(w2, q2[2].z, w3 * q2[3].z);

        rr = fmaf(T, sr, rr);
        gg = fmaf(T, sg, gg);
        bb = fmaf(T, sb, bb);
        T *= P;

        if (T < 1e-5f) break;
    }

    const int idx = (pyi * IMG + pxi) * 3;
    out[idx + 0] = rr;
    out[idx + 1] = gg;
    out[idx + 2] = bb;
}

extern "C" void kernel_launch(void* const* d_in, const int* in_sizes, int n_in,
                              void* d_out, int out_size)
{
    const float* pos   = (const float*)d_in[0];  // (512,3)
    const float* cov3d = (const float*)d_in[1];  // (512,3,3)
    const float* opac  = (const float*)d_in[2];  // (512,1)
    const float* cols  = (const float*)d_in[3];  // (512,3)
    const float* Km    = (const float*)d_in[4];  // (3,3)
    const float* Rm    = (const float*)d_in[5];  // (3,3)
    const float* tv    = (const float*)d_in[6];  // (3,)
    float* out = (float*)d_out;                  // (256,256,3)

    gs_fused<<<dim3(IMG/TW, IMG/TH), NT>>>(pos, cov3d, opac, cols, Km, Rm, tv, out);
}